// round 2
// baseline (speedup 1.0000x reference)
#include <cuda_runtime.h>
#include <cstddef>

#define IMH 1024
#define IMW 1024
#define SFRAMES 8
#define TR 32            // tile rows
#define TC 128           // tile cols
#define NTHREADS 512
#define GW (TC + 8)      // 136: gray tile width incl halo
#define GH (TR + 8)      // 40:  gray tile height incl halo

// padded index for tmp arrays: breaks stride-4 bank pattern (stride becomes 5, coprime w/ 32)
__device__ __forceinline__ int padi(int i) { return i + (i >> 2); }

#define TPAD ((TR * GW) + ((TR * GW) >> 2))      // padded tmp array size (floats)
#define SMEM_BYTES ((GH * GW + 2 * TPAD) * 4)

__device__ __forceinline__ int reflect101(int i, int n) {
    if (i < 0) i = -i;
    if (i >= n) i = 2 * n - 2 - i;
    return i;
}

extern "C" __global__ void __launch_bounds__(NTHREADS)
lap_merge_kernel(const float* __restrict__ x, float* __restrict__ out)
{
    extern __shared__ float smem[];
    float* sG  = smem;                  // GH*GW gray tile (+halo)
    float* sTA = smem + GH * GW;        // padded TR*GW vertical-A
    float* sTB = sTA + TPAD;            // padded TR*GW vertical-B

    const int tid = threadIdx.x;
    const int b   = blockIdx.z;
    const int hr0 = blockIdx.y * TR;
    const int wc0 = blockIdx.x * TC;
    const size_t HW = (size_t)IMH * IMW;

    // per-thread running state: 2 iterations x 4 consecutive cols each
    float bestLap[2][4], bR[2][4], bG[2][4], bB[2][4];
#pragma unroll
    for (int it = 0; it < 2; it++)
#pragma unroll
        for (int o = 0; o < 4; o++) bestLap[it][o] = -3.0e38f;

    for (int s = 0; s < SFRAMES; s++) {
        const float* __restrict__ xf = x + ((size_t)(b * SFRAMES + s)) * 3 * HW;

        // ---- Phase 1: gray (mean of 3 channels) into smem, reflect-101 halo ----
        for (int i = tid; i < GH * GW; i += NTHREADS) {
            int r = i / GW;
            int c = i - r * GW;
            int gr = reflect101(hr0 - 4 + r, IMH);
            int gc = reflect101(wc0 - 4 + c, IMW);
            size_t off = (size_t)gr * IMW + gc;
            float v = (__ldg(xf + off) + __ldg(xf + off + HW) + __ldg(xf + off + 2 * HW)) / 3.0f;
            sG[i] = v;
        }
        __syncthreads();

        // ---- Phase 2: vertical 9-tap A and B (4-row blocking per thread) ----
        // A/16 = [1,8,28,56,70,...]  B/16 = [1,4,4,-4,-10,...]
        for (int t = tid; t < (TR / 4) * GW; t += NTHREADS) {
            int rg = t / GW;
            int c  = t - rg * GW;
            float g[12];
#pragma unroll
            for (int j = 0; j < 12; j++) g[j] = sG[(rg * 4 + j) * GW + c];
#pragma unroll
            for (int o = 0; o < 4; o++) {
                float p1 = g[o + 3] + g[o + 5];
                float p2 = g[o + 2] + g[o + 6];
                float p3 = g[o + 1] + g[o + 7];
                float p4 = g[o + 0] + g[o + 8];
                float ctr = g[o + 4];
                float tA =  4.375f * ctr + 3.5f  * p1 + 1.75f * p2 + 0.5f  * p3 + 0.0625f * p4;
                float tB = -0.625f * ctr - 0.25f * p1 + 0.25f * p2 + 0.25f * p3 + 0.0625f * p4;
                int oi = (rg * 4 + o) * GW + c;
                sTA[padi(oi)] = tA;
                sTB[padi(oi)] = tB;
            }
        }
        __syncthreads();

        // ---- Phase 3: horizontal (B on tA + A on tB), running argmax + RGB ----
#pragma unroll
        for (int it = 0; it < 2; it++) {
            int t  = tid + it * NTHREADS;      // < TR*32 = 1024 exactly
            int r  = t >> 5;
            int cg = t & 31;
            int base = r * GW + cg * 4;
            float va[12], vb[12];
#pragma unroll
            for (int j = 0; j < 12; j++) {
                va[j] = sTA[padi(base + j)];
                vb[j] = sTB[padi(base + j)];
            }
            int gr = hr0 + r;
#pragma unroll
            for (int o = 0; o < 4; o++) {
                float lap =
                      4.375f  * vb[o + 4] - 0.625f * va[o + 4]
                    + 3.5f    * (vb[o + 3] + vb[o + 5]) - 0.25f * (va[o + 3] + va[o + 5])
                    + 1.75f   * (vb[o + 2] + vb[o + 6]) + 0.25f * (va[o + 2] + va[o + 6])
                    + 0.5f    * (vb[o + 1] + vb[o + 7]) + 0.25f * (va[o + 1] + va[o + 7])
                    + 0.0625f * (vb[o + 0] + vb[o + 8]) + 0.0625f * (va[o + 0] + va[o + 8]);
                if (lap > bestLap[it][o]) {      // strict > keeps first frame on ties (argmax semantics)
                    bestLap[it][o] = lap;
                    int gc = wc0 + cg * 4 + o;
                    size_t off = (size_t)gr * IMW + gc;
                    bR[it][o] = __ldg(xf + off);
                    bG[it][o] = __ldg(xf + off + HW);
                    bB[it][o] = __ldg(xf + off + 2 * HW);
                }
            }
        }
        __syncthreads();   // protect smem reuse by next frame
    }

    // ---- Epilogue: write (b, c, h, w) as float4 per channel ----
#pragma unroll
    for (int it = 0; it < 2; it++) {
        int t  = tid + it * NTHREADS;
        int r  = t >> 5;
        int cg = t & 31;
        int gr = hr0 + r;
        int gc = wc0 + cg * 4;
        size_t base = ((size_t)(b * 3) * IMH + gr) * IMW + gc;
        float4 q;
        q = make_float4(bR[it][0], bR[it][1], bR[it][2], bR[it][3]);
        *reinterpret_cast<float4*>(out + base) = q;
        q = make_float4(bG[it][0], bG[it][1], bG[it][2], bG[it][3]);
        *reinterpret_cast<float4*>(out + base + HW) = q;
        q = make_float4(bB[it][0], bB[it][1], bB[it][2], bB[it][3]);
        *reinterpret_cast<float4*>(out + base + 2 * HW) = q;
    }
}

extern "C" void kernel_launch(void* const* d_in, const int* in_sizes, int n_in,
                              void* d_out, int out_size)
{
    const float* x = (const float*)d_in[0];
    float* out = (float*)d_out;
    int nb = in_sizes[0] / (SFRAMES * 3 * IMH * IMW);   // = 4

    cudaFuncSetAttribute(lap_merge_kernel,
                         cudaFuncAttributeMaxDynamicSharedMemorySize, SMEM_BYTES);

    dim3 grid(IMW / TC, IMH / TR, nb);
    lap_merge_kernel<<<grid, NTHREADS, SMEM_BYTES>>>(x, out);
}